// round 9
// baseline (speedup 1.0000x reference)
#include <cuda_runtime.h>
#include <math.h>

#define NQ   32
#define MM   32
#define ND_  200
#define NN   160
#define HH   768
#define DIMV 128
#define NEGV (-10000.0f)

typedef unsigned long long ull;

// Packed dual-FMA (sm_100+): acc.lo += a.lo*b.lo ; acc.hi += a.hi*b.hi.
#define FMA2(acc, a, b) \
    asm("fma.rn.f32x2 %0, %1, %2, %0;" : "+l"(acc) : "l"(a), "l"(b))

// Scratch (no cudaMalloc allowed): projected+normalized embeddings.
__device__ float g_Qp[NQ * MM * DIMV];     // 0.5 MB
__device__ float g_Dp[ND_ * NN * DIMV];    // 16.4 MB (stays L2-resident)

// ---------------------------------------------------------------------------
// Projection + L2-normalize for BOTH Q and D. 258 blocks x 512 threads,
// block = 128 rows x 128 cols. Warp tile 16m x 64n: mw=warp>>1, nh=warp&1,
// lane: lh=lane>>4 (8 rows each), ln=lane&15 (4 cols each).
// Both X and W staged k-major with per-8-row +16B group pad:
//   addr(r,k) = r*36 + ((r>>3)<<2) + k   -> LDS.128 k-quads, conflict-free.
// Per k-quad/warp: a 8 loads (2 addrs, 1 wf) + b 4 loads (16 addrs spread
// over 16B slots twice each -> 2 wf) = 16 wf per 64 FMA2.
// ---------------------------------------------------------------------------
__global__ __launch_bounds__(512) void proj_kernel(
    const float* __restrict__ Qx, const float* __restrict__ Dx,
    const float* __restrict__ W,
    float* __restrict__ Qy, float* __restrict__ Dy)
{
    __shared__ __align__(16) float Xs[4672];   // 128*36 + 16*4
    __shared__ __align__(16) float Wt[4672];
    __shared__ float ssb[128 * 2];             // per-row partial sumsq halves

    const int bx = blockIdx.x;
    const float* X; float* Y; size_t row0;
    if (bx < 8) { X = Qx; Y = Qy; row0 = (size_t)bx * 128; }
    else        { X = Dx; Y = Dy; row0 = (size_t)(bx - 8) * 128; }

    const int tid  = threadIdx.x;
    const int warp = tid >> 5;
    const int lane = tid & 31;
    const int mw   = warp >> 1;      // 0..7  -> rows mw*16 .. +15
    const int nh   = warp & 1;       // 0..1  -> cols nh*64 .. +63
    const int lh   = lane >> 4;      // 0..1  -> 8-row half
    const int ln   = lane & 15;      // 0..15 -> 4-col group

    ull acc2[8][4];
#pragma unroll
    for (int i = 0; i < 8; i++)
#pragma unroll
        for (int j = 0; j < 4; j++) acc2[i][j] = 0ull;

    const int aBaseI = (mw * 16 + lh * 8) * 36 + ((mw * 2 + lh) << 2);
    const int bBaseI = (nh * 64 + ln * 4) * 36 + ((nh * 8 + (ln >> 1)) << 2);

    for (int kt = 0; kt < HH; kt += 32) {
        // Xs: idx -> r = idx>>5, k = idx&31 (coalesced gmem reads)
#pragma unroll
        for (int t = 0; t < 8; t++) {
            int idx = tid + 512 * t;
            int r = idx >> 5, k = idx & 31;
            Xs[r * 36 + ((r >> 3) << 2) + k] = X[(row0 + r) * HH + kt + k];
        }
        // Wt: k-major transpose; idx -> n = idx&127, k = idx>>7
#pragma unroll
        for (int t = 0; t < 8; t++) {
            int idx = tid + 512 * t;
            int n = idx & 127, k = idx >> 7;
            Wt[n * 36 + ((n >> 3) << 2) + k] = W[(size_t)(kt + k) * DIMV + n];
        }
        __syncthreads();

#pragma unroll
        for (int k = 0; k < 32; k += 4) {
            ulonglong2 a4[8], b4[4];
#pragma unroll
            for (int i = 0; i < 8; i++)
                a4[i] = *(const ulonglong2*)&Xs[aBaseI + i * 36 + k];
#pragma unroll
            for (int j = 0; j < 4; j++)
                b4[j] = *(const ulonglong2*)&Wt[bBaseI + j * 36 + k];
#pragma unroll
            for (int i = 0; i < 8; i++)
#pragma unroll
                for (int j = 0; j < 4; j++) {
                    FMA2(acc2[i][j], a4[i].x, b4[j].x);
                    FMA2(acc2[i][j], a4[i].y, b4[j].y);
                }
        }
        __syncthreads();
    }

    // Row norm: each row's 128 cols span 2 warps (nh) x 16 lanes (ln) x 4 j.
    float y[8][4];
#pragma unroll
    for (int i = 0; i < 8; i++) {
        float ssp = 0.0f;
#pragma unroll
        for (int j = 0; j < 4; j++) {
            float lo, hi;
            asm("mov.b64 {%0,%1}, %2;" : "=f"(lo), "=f"(hi) : "l"(acc2[i][j]));
            y[i][j] = lo + hi;
            ssp += y[i][j] * y[i][j];
        }
#pragma unroll
        for (int off = 8; off >= 1; off >>= 1)
            ssp += __shfl_xor_sync(0xffffffffu, ssp, off);  // reduce over ln
        if (ln == 0) ssb[(mw * 16 + lh * 8 + i) * 2 + nh] = ssp;
    }
    __syncthreads();

#pragma unroll
    for (int i = 0; i < 8; i++) {
        int r = mw * 16 + lh * 8 + i;
        float ss = ssb[r * 2] + ssb[r * 2 + 1];
        float inv = 1.0f / fmaxf(sqrtf(ss), 1e-12f);
        float4 v = make_float4(y[i][0] * inv, y[i][1] * inv,
                               y[i][2] * inv, y[i][3] * inv);
        *(float4*)&Y[(row0 + r) * DIMV + nh * 64 + ln * 4] = v;
    }
}

// ---------------------------------------------------------------------------
// Fused scoring kernel: one block per (q,d). 256 threads, 2 blocks/SM.
// Warp tile 8m x 80n: mg=warp>>1, nh=warp&1.
// lane: lh=lane>>3 (4 groups of 2 rows), ln=lane&7 (8 groups of 10 n).
// Dp smem: DPS=132 words/row + 16B pad per 10-row group ->
//   b LDS.128: 8 distinct addrs, slot step 3 (mod 8) -> 1 wf, conflict-free.
//   a LDS.128: 4 distinct addrs, slot step 2 -> 1 wf.
// Per k-quad/warp: 12 wf + 40 FMA2 (issue-bound, not crossbar-bound).
// ---------------------------------------------------------------------------
#define DPS 132
#define QPS 132
__global__ __launch_bounds__(256, 2) void score_kernel(
    const float* __restrict__ gumbel,
    const float* __restrict__ q_mask,
    const float* __restrict__ d_mask,
    float* __restrict__ out)
{
    extern __shared__ float smem[];
    float* Dp_s    = smem;                     // 160*132 + 16*4 = 21184
    float* Qp_s    = Dp_s + NN * DPS + 64;     // [32][132]
    float* dmask_s = Qp_s + MM * QPS;          // [160]
    float* qmask_s = dmask_s + NN;             // [32]
    float* zbuf    = qmask_s + MM;             // [32][2]
    float* sbuf    = zbuf + 64;                // [32][2]

    const int bx   = blockIdx.x;               // q*200 + d
    const int d    = bx % ND_;
    const int q    = bx / ND_;
    const int tid  = threadIdx.x;
    const int warp = tid >> 5;                 // 0..7
    const int lane = tid & 31;
    const int mg   = warp >> 1;                // 0..3
    const int nh   = warp & 1;                 // 0..1
    const int lh   = lane >> 3;                // 0..3 -> 2 rows each
    const int ln   = lane & 7;                 // 0..7 -> 10 n each

    // Prefetch this thread's 20 gumbel values early (hides DRAM latency
    // behind tile loads + the whole k-loop).
    const float* gb = gumbel + (size_t)bx * MM * NN;
    float gpre[2][10];
#pragma unroll
    for (int i = 0; i < 2; i++) {
        const int m = mg * 8 + lh * 2 + i;
#pragma unroll
        for (int j = 0; j < 10; j++)
            gpre[i][j] = gb[m * NN + nh * 80 + ln * 10 + j];
    }

    // Load Dp[d]: 10240 float2, group-padded layout addr = n*132+(n/10)*4.
    {
        const float2* Dg = (const float2*)(g_Dp + (size_t)d * NN * DIMV);
#pragma unroll
        for (int it = 0; it < 40; it++) {
            int idx2 = tid + 256 * it;
            int n = idx2 >> 6, k2 = idx2 & 63;
            int g = (n * 205) >> 11;          // n/10 for n<160
            *(float2*)&Dp_s[n * DPS + (g << 2) + 2 * k2] = Dg[idx2];
        }
    }
    // Load Qp[q]: 1024 float4.
    {
        const float4* Qg = (const float4*)(g_Qp + (size_t)q * MM * DIMV);
#pragma unroll
        for (int it = 0; it < 4; it++) {
            int idx4 = tid + 256 * it;
            int m = idx4 >> 5, k4 = idx4 & 31;
            *(float4*)&Qp_s[m * QPS + 4 * k4] = Qg[idx4];
        }
    }
    if (tid < NN) dmask_s[tid] = d_mask[(size_t)d * NN + tid];
    if (tid < MM) qmask_s[tid] = q_mask[(size_t)q * MM + tid];
    __syncthreads();

    // 2m x 10n register tile, f32x2 over k-pairs, LDS.128 k-quads.
    ull acc2[2][10];
#pragma unroll
    for (int i = 0; i < 2; i++)
#pragma unroll
        for (int j = 0; j < 10; j++) acc2[i][j] = 0ull;

    const float* Qrow = Qp_s + (mg * 8 + lh * 2) * QPS;
    const float* Drow = Dp_s + (nh * 80 + ln * 10) * DPS + ((nh * 8 + ln) << 2);

#pragma unroll 2
    for (int k = 0; k < DIMV; k += 4) {
        ulonglong2 a4[2], b4[10];
#pragma unroll
        for (int i = 0; i < 2; i++)
            a4[i] = *(const ulonglong2*)&Qrow[i * QPS + k];
#pragma unroll
        for (int j = 0; j < 10; j++)
            b4[j] = *(const ulonglong2*)&Drow[j * DPS + k];
#pragma unroll
        for (int i = 0; i < 2; i++)
#pragma unroll
            for (int j = 0; j < 10; j++) {
                FMA2(acc2[i][j], a4[i].x, b4[j].x);
                FMA2(acc2[i][j], a4[i].y, b4[j].y);
            }
    }

    // Epilogue: mask, gumbel-argmax per m over this warp's 80 n, combine.
#pragma unroll
    for (int i = 0; i < 2; i++) {
        const int m = mg * 8 + lh * 2 + i;
        float bestz = -3.0e38f, bests = 0.0f;
#pragma unroll
        for (int j = 0; j < 10; j++) {
            const int n = nh * 80 + ln * 10 + j;
            float lo, hi;
            asm("mov.b64 {%0,%1}, %2;" : "=f"(lo), "=f"(hi) : "l"(acc2[i][j]));
            float sim = lo + hi;
            float dm = dmask_s[n];
            float sv = sim * dm + (1.0f - dm) * NEGV;   // exact select
            float z  = sv * 10.0f + gpre[i][j];         // TEMP=0.1
            if (z > bestz) { bestz = z; bests = sv; }
        }
        // reduce over ln (lane bits 0..2); lh bits preserved
#pragma unroll
        for (int off = 4; off >= 1; off >>= 1) {
            float zo = __shfl_xor_sync(0xffffffffu, bestz, off);
            float so = __shfl_xor_sync(0xffffffffu, bests, off);
            if (zo > bestz) { bestz = zo; bests = so; }
        }
        if (ln == 0) { zbuf[m * 2 + nh] = bestz; sbuf[m * 2 + nh] = bests; }
    }
    __syncthreads();

    if (warp == 0) {
        const int m = lane;
        float z0 = zbuf[2 * m], z1 = zbuf[2 * m + 1];
        float s  = (z1 > z0) ? sbuf[2 * m + 1] : sbuf[2 * m];
        float p  = qmask_s[m] * s;
#pragma unroll
        for (int off = 16; off >= 1; off >>= 1)
            p += __shfl_xor_sync(0xffffffffu, p, off);
        if (lane == 0) out[bx] = p;
    }
}

// ---------------------------------------------------------------------------
extern "C" void kernel_launch(void* const* d_in, const int* in_sizes, int n_in,
                              void* d_out, int out_size)
{
    const float* Q      = (const float*)d_in[0];  // (32,32,768)
    const float* D      = (const float*)d_in[1];  // (200,160,768)
    const float* q_mask = (const float*)d_in[2];  // (32,32)
    const float* d_mask = (const float*)d_in[3];  // (200,160)
    const float* gumbel = (const float*)d_in[4];  // (32,200,32,160)
    const float* W      = (const float*)d_in[5];  // (768,128)
    float* out = (float*)d_out;                   // (32,200)

    float* Qp; cudaGetSymbolAddress((void**)&Qp, g_Qp);
    float* Dp; cudaGetSymbolAddress((void**)&Dp, g_Dp);

    // Combined projection: 8 Q-blocks + 250 D-blocks of 128 rows each.
    proj_kernel<<<258, 512>>>(Q, D, W, Qp, Dp);

    // Fused sim + gumbel-argmax + score. ~101 KB smem -> 2 blocks/SM.
    const int smem_bytes =
        (NN * DPS + 64 + MM * QPS + NN + MM + 64 + 64) * sizeof(float);
    cudaFuncSetAttribute(score_kernel,
                         cudaFuncAttributeMaxDynamicSharedMemorySize, smem_bytes);
    score_kernel<<<NQ * ND_, 256, smem_bytes>>>(gumbel, q_mask, d_mask, out);
}

// round 10
// speedup vs baseline: 1.1997x; 1.1997x over previous
#include <cuda_runtime.h>
#include <math.h>

#define NQ   32
#define MM   32
#define ND_  200
#define NN   160
#define HH   768
#define DIMV 128
#define NEGV (-10000.0f)

typedef unsigned long long ull;

// Packed dual-FMA (sm_100+): acc.lo += a.lo*b.lo ; acc.hi += a.hi*b.hi.
#define FMA2(acc, a, b) \
    asm("fma.rn.f32x2 %0, %1, %2, %0;" : "+l"(acc) : "l"(a), "l"(b))
// Duplicate a scalar float into both halves of an f32x2.
#define PACK2(dst, x) \
    asm("mov.b64 %0, {%1, %1};" : "=l"(dst) : "f"(x))

// Scratch (no cudaMalloc allowed).
__device__ float g_QpT[NQ * DIMV * MM];    // [q][k][m]  (k-major TRANSPOSED)
__device__ float g_Dp[ND_ * NN * DIMV];    // [d][n][k]

// Group-padded row offsets (float words): +16B pad every 8 rows so rows 8
// apart land 4 banks apart -> conflict-free multi-row LDS.
#define PADX(r)  ((r) * 36 + (((r) >> 3) << 2))    // proj tiles (32 k cols)
#define PADD(n)  ((n) * 132 + (((n) >> 3) << 2))   // score Dp (128 k cols)

// ---------------------------------------------------------------------------
// Projection + row L2-normalize for BOTH Q and D. 516 blocks x 128 threads.
// Block = 64 rows x 128 cols. Warps 2x2 (wm,wn), lanes 4x8 (lm,ln),
// thread tile 8m x 8n, k-packed f32x2 (acc2[8][8]).
// Q output written TRANSPOSED to g_QpT[q][k][m]; D output k-major to g_Dp.
// ---------------------------------------------------------------------------
__global__ __launch_bounds__(128) void proj_kernel(
    const float* __restrict__ Qx, const float* __restrict__ Dx,
    const float* __restrict__ W,
    float* __restrict__ QyT, float* __restrict__ Dy)
{
    __shared__ __align__(16) float Xs[64 * 36 + 32];    // PADX layout
    __shared__ __align__(16) float Wt[128 * 36 + 64];   // k-major W, PADX
    __shared__ float ssb[64 * 2];

    const int bx = blockIdx.x;
    const bool isQ = bx < 16;
    const float* X = isQ ? Qx : Dx;
    const size_t row0 = isQ ? (size_t)bx * 64 : (size_t)(bx - 16) * 64;

    const int tid  = threadIdx.x;
    const int warp = tid >> 5, lane = tid & 31;
    const int wm = warp >> 1, wn = warp & 1;   // warp tile 32m x 64n
    const int lm = lane >> 3, ln = lane & 7;   // lane tile 8m x 8n

    ull acc2[8][8];
#pragma unroll
    for (int i = 0; i < 8; i++)
#pragma unroll
        for (int j = 0; j < 8; j++) acc2[i][j] = 0ull;

    const int aB = PADX(wm * 32 + lm * 8);     // +i*36 +k (8-row group)
    const int bB = PADX(wn * 64 + ln * 8);

    for (int kt = 0; kt < HH; kt += 32) {
        // Xs: 64x32 via float4 (512 float4, 4/thread), coalesced.
#pragma unroll
        for (int t = 0; t < 4; t++) {
            int idx4 = tid + 128 * t;
            int r = idx4 >> 3, k4 = (idx4 & 7) << 2;
            float4 v = *(const float4*)&X[(row0 + r) * HH + kt + k4];
            *(float4*)&Xs[PADX(r) + k4] = v;
        }
        // Wt: k-major transpose of W chunk (32k x 128n), scatter STS.32.
#pragma unroll
        for (int t = 0; t < 8; t++) {
            int idx4 = tid + 128 * t;
            int k = idx4 >> 5, nb = (idx4 & 31) << 2;
            float4 v = ((const float4*)W)[(size_t)(kt + k) * 32 + (idx4 & 31)];
            int base = PADX(nb) + k;           // nb..nb+3 same 8-group
            Wt[base]          = v.x;
            Wt[base + 36]     = v.y;
            Wt[base + 72]     = v.z;
            Wt[base + 108]    = v.w;
        }
        __syncthreads();

#pragma unroll 4
        for (int k = 0; k < 32; k += 2) {
            ull a2[8], b2[8];
#pragma unroll
            for (int i = 0; i < 8; i++)
                a2[i] = *(const ull*)&Xs[aB + i * 36 + k];
#pragma unroll
            for (int j = 0; j < 8; j++)
                b2[j] = *(const ull*)&Wt[bB + j * 36 + k];
#pragma unroll
            for (int i = 0; i < 8; i++)
#pragma unroll
                for (int j = 0; j < 8; j++) FMA2(acc2[i][j], a2[i], b2[j]);
        }
        __syncthreads();
    }

    // Row L2 norm: row's 128 cols span wn(2) x ln(8) x j(8).
    float y[8][8];
#pragma unroll
    for (int i = 0; i < 8; i++) {
        float ss = 0.0f;
#pragma unroll
        for (int j = 0; j < 8; j++) {
            float lo, hi;
            asm("mov.b64 {%0,%1}, %2;" : "=f"(lo), "=f"(hi) : "l"(acc2[i][j]));
            y[i][j] = lo + hi;
            ss += y[i][j] * y[i][j];
        }
#pragma unroll
        for (int off = 4; off >= 1; off >>= 1)
            ss += __shfl_xor_sync(0xffffffffu, ss, off);   // reduce over ln
        if (ln == 0) ssb[(wm * 32 + lm * 8 + i) * 2 + wn] = ss;
    }
    __syncthreads();

#pragma unroll
    for (int i = 0; i < 8; i++) {
        int r = wm * 32 + lm * 8 + i;
        float ss = ssb[r * 2] + ssb[r * 2 + 1];
        float inv = 1.0f / fmaxf(sqrtf(ss), 1e-12f);
        if (isQ) {
            size_t gr = row0 + r;
            int q = (int)(gr >> 5), m = (int)(gr & 31);
#pragma unroll
            for (int j = 0; j < 8; j++)
                QyT[((size_t)q * DIMV + wn * 64 + ln * 8 + j) * MM + m] =
                    y[i][j] * inv;
        } else {
            float4 v0 = make_float4(y[i][0]*inv, y[i][1]*inv, y[i][2]*inv, y[i][3]*inv);
            float4 v1 = make_float4(y[i][4]*inv, y[i][5]*inv, y[i][6]*inv, y[i][7]*inv);
            float* dst = Dy + (row0 + r) * DIMV + wn * 64 + ln * 8;
            *(float4*)dst = v0;
            *(float4*)(dst + 4) = v1;
        }
    }
}

// ---------------------------------------------------------------------------
// Fused scoring: block = (4 q's, 1 d). Grid 1600, 320 threads (10 warps),
// 1 block/SM. Tile 128m x 160n x 128k. Warps 2x5 (wm,wn), lanes 8x4 (lm,ln),
// thread tile 8m x 8n. Accumulators m-packed f32x2 (acc2[4 m-pairs][8 n]).
//  a: LDS.64 m-pairs from k-major-transposed Qp tile [k][128m]
//  b: LDS.32 scalar from Dp [n][k] (PADD), duplicated via mov.b64
// Per SM/k: 10 warps x 16 wf = 160 = FMA 10x32x2/4 = 160 -> balanced.
// ---------------------------------------------------------------------------
__global__ __launch_bounds__(320, 1) void score_kernel(
    const float* __restrict__ gumbel,
    const float* __restrict__ q_mask,
    const float* __restrict__ d_mask,
    float* __restrict__ out)
{
    extern __shared__ float smem[];
    float* Dp_s    = smem;                      // PADD: 21200 floats
    float* Qp_ts   = Dp_s + 21200;              // [128k][128m]
    float* dmask_s = Qp_ts + DIMV * 128;        // [160]
    float* qmask_s = dmask_s + NN;              // [128] (4q x 32m)
    float* zbuf    = qmask_s + 128;             // [128][5]
    float* sbuf    = zbuf + 640;                // [128][5]

    const int bx = blockIdx.x;                  // qg*200 + d
    const int d  = bx % ND_;
    const int qg = bx / ND_;                    // 0..7 (4 q's each)
    const int tid  = threadIdx.x;
    const int warp = tid >> 5, lane = tid & 31;
    const int wm = warp / 5, wn = warp % 5;     // warp tile 64m x 32n
    const int lm = lane >> 2, ln = lane & 3;    // lane tile 8m x 8n
    const int mBase = wm * 64 + lm * 8;         // block-local m row 0..127
    const int nBase = wn * 32 + ln * 8;         // n 0..159

    // Load Dp[d]: 20480 floats = 10240 float2, 32/thread.
    {
        const float2* Dg = (const float2*)(g_Dp + (size_t)d * NN * DIMV);
#pragma unroll
        for (int it = 0; it < 32; it++) {
            int idx2 = tid + 320 * it;
            int n = idx2 >> 6, k2 = idx2 & 63;
            *(float2*)&Dp_s[PADD(n) + 2 * k2] = Dg[idx2];
        }
    }
    // Load Qp_ts: 4 q's worth of [k][32m] -> [k][128] tile. 4096 float4.
    {
        const float4* Qg = (const float4*)(g_QpT + (size_t)qg * 4 * DIMV * MM);
        for (int it = 0; it < 13; it++) {
            int s = tid + 320 * it;
            if (s < 4096) {
                int qi = s >> 10, k = (s >> 3) & 127, m4 = (s & 7) << 2;
                float4 v = Qg[s];
                *(float4*)&Qp_ts[k * 128 + qi * 32 + m4] = v;
            }
        }
    }
    if (tid < NN)  dmask_s[tid] = d_mask[(size_t)d * NN + tid];
    if (tid < 128) qmask_s[tid] = q_mask[(size_t)qg * 128 + tid];
    __syncthreads();

    ull acc2[4][8];
#pragma unroll
    for (int ip = 0; ip < 4; ip++)
#pragma unroll
        for (int j = 0; j < 8; j++) acc2[ip][j] = 0ull;

    const int bOff = PADD(nBase);               // +132*j +k (8-row group)

#pragma unroll 2
    for (int k = 0; k < DIMV; k++) {
        ull a2[4], b2[8];
        const float* Ak = Qp_ts + k * 128 + mBase;
#pragma unroll
        for (int ip = 0; ip < 4; ip++)
            a2[ip] = *(const ull*)&Ak[2 * ip];          // m-pair, CF
#pragma unroll
        for (int j = 0; j < 8; j++) {
            float b = Dp_s[bOff + 132 * j + k];         // 4 banks + bcast
            PACK2(b2[j], b);
        }
#pragma unroll
        for (int ip = 0; ip < 4; ip++)
#pragma unroll
            for (int j = 0; j < 8; j++) FMA2(acc2[ip][j], a2[ip], b2[j]);
    }

    // Epilogue: per m-row, mask + gumbel-argmax over thread's 8 n,
    // reduce over ln (4 lanes), stash per n-warp, combine across 5 wn.
#pragma unroll
    for (int ip = 0; ip < 4; ip++) {
        float slo[8], shi[8];
#pragma unroll
        for (int j = 0; j < 8; j++)
            asm("mov.b64 {%0,%1}, %2;"
                : "=f"(slo[j]), "=f"(shi[j]) : "l"(acc2[ip][j]));
#pragma unroll
        for (int h = 0; h < 2; h++) {
            const int r = mBase + 2 * ip + h;           // local row 0..127
            const int qi = r >> 5, m = r & 31;
            const float* gp = gumbel +
                (((size_t)(qg * 4 + qi) * ND_ + d) * MM + m) * NN + nBase;
            float4 g0 = *(const float4*)gp;
            float4 g1 = *(const float4*)(gp + 4);
            float gv[8] = {g0.x, g0.y, g0.z, g0.w, g1.x, g1.y, g1.z, g1.w};
            float bestz = -3.0e38f, bests = 0.0f;
#pragma unroll
            for (int j = 0; j < 8; j++) {
                float sim = h ? shi[j] : slo[j];
                float dm = dmask_s[nBase + j];
                float sv = sim * dm + (1.0f - dm) * NEGV;  // exact select
                float z  = sv * 10.0f + gv[j];             // TEMP=0.1
                if (z > bestz) { bestz = z; bests = sv; }
            }
#pragma unroll
            for (int off = 2; off >= 1; off >>= 1) {       // reduce over ln
                float zo = __shfl_xor_sync(0xffffffffu, bestz, off);
                float so = __shfl_xor_sync(0xffffffffu, bests, off);
                if (zo > bestz) { bestz = zo; bests = so; }
            }
            if (ln == 0) { zbuf[r * 5 + wn] = bestz; sbuf[r * 5 + wn] = bests; }
        }
    }
    __syncthreads();

    // Combine 5 n-warps per row; warp w (0..3) = q index qi = w.
    if (tid < 128) {
        const int r = tid;
        float bz = zbuf[r * 5], bs = sbuf[r * 5];
#pragma unroll
        for (int w = 1; w < 5; w++) {
            float z = zbuf[r * 5 + w];
            if (z > bz) { bz = z; bs = sbuf[r * 5 + w]; }
        }
        float p = qmask_s[r] * bs;
#pragma unroll
        for (int off = 16; off >= 1; off >>= 1)
            p += __shfl_xor_sync(0xffffffffu, p, off);
        if ((tid & 31) == 0)
            out[(size_t)(qg * 4 + (r >> 5)) * ND_ + d] = p;
    }
}

// ---------------------------------------------------------------------------
extern "C" void kernel_launch(void* const* d_in, const int* in_sizes, int n_in,
                              void* d_out, int out_size)
{
    const float* Q      = (const float*)d_in[0];  // (32,32,768)
    const float* D      = (const float*)d_in[1];  // (200,160,768)
    const float* q_mask = (const float*)d_in[2];  // (32,32)
    const float* d_mask = (const float*)d_in[3];  // (200,160)
    const float* gumbel = (const float*)d_in[4];  // (32,200,32,160)
    const float* W      = (const float*)d_in[5];  // (768,128)
    float* out = (float*)d_out;                   // (32,200)

    float* QpT; cudaGetSymbolAddress((void**)&QpT, g_QpT);
    float* Dp;  cudaGetSymbolAddress((void**)&Dp,  g_Dp);

    // Combined projection: 16 Q-blocks + 500 D-blocks of 64 rows each.
    proj_kernel<<<516, 128>>>(Q, D, W, QpT, Dp);

    // Fused sim + gumbel-argmax + score: (4q,1d) tiles.
    const int smem_bytes =
        (21200 + DIMV * 128 + NN + 128 + 640 + 640) * sizeof(float);
    cudaFuncSetAttribute(score_kernel,
                         cudaFuncAttributeMaxDynamicSharedMemorySize, smem_bytes);
    score_kernel<<<(NQ / 4) * ND_, 320, smem_bytes>>>(gumbel, q_mask, d_mask, out);
}

// round 12
// speedup vs baseline: 1.6265x; 1.3557x over previous
#include <cuda_runtime.h>
#include <math.h>
#include <stdint.h>

#define NQ   32
#define MM   32
#define ND_  200
#define NN   160
#define HH   768
#define DIMV 128
#define NEGV (-10000.0f)

// ---------------------------------------------------------------------------
// Scratch (no cudaMalloc allowed): tf32 hi/lo splits.
// ---------------------------------------------------------------------------
__device__ float g_Qh[NQ * MM * DIMV];     // [m_global][k] row-major
__device__ float g_Ql[NQ * MM * DIMV];
__device__ float g_Dh[ND_ * NN * DIMV];    // [d*160+n][k]
__device__ float g_Dl[ND_ * NN * DIMV];
__device__ float g_WTh[DIMV * HH];         // W transposed: [n][k], tf32 hi
__device__ float g_WTl[DIMV * HH];         // lo

__device__ __forceinline__ float tf32_rna(float x) {
    uint32_t u;
    asm("cvt.rna.tf32.f32 %0, %1;" : "=r"(u) : "f"(x));
    return __uint_as_float(u);
}

// Warp-level tensor-core MMA (sm_80+ baseline PTX -> works on compute_103):
// C[16x8] += A[16x8] * B[8x8], A row-major, B col-major ([n][k]), tf32 in,
// f32 accumulate. a/b registers hold tf32 bit patterns.
__device__ __forceinline__ void mma_tf32(float* c, const uint32_t* a,
                                         const uint32_t* b) {
    asm("mma.sync.aligned.m16n8k8.row.col.f32.tf32.tf32.f32 "
        "{%0,%1,%2,%3}, {%4,%5,%6,%7}, {%8,%9}, {%0,%1,%2,%3};"
        : "+f"(c[0]), "+f"(c[1]), "+f"(c[2]), "+f"(c[3])
        : "r"(a[0]), "r"(a[1]), "r"(a[2]), "r"(a[3]), "r"(b[0]), "r"(b[1]));
}

#define B32(x) __float_as_uint(x)
#define PS 36   // k-chunk smem row stride (36 mod 32 = 4 -> fragment LDS
                // addrs (4*g + t) are a 32-lane bank permutation: CF)

// ---------------------------------------------------------------------------
// Prep: split + transpose W once. grid 384 x 256.
// ---------------------------------------------------------------------------
__global__ void wsplit_kernel(const float* __restrict__ W,
                              float* __restrict__ WTh, float* __restrict__ WTl)
{
    int idx = blockIdx.x * 256 + threadIdx.x;
    if (idx < HH * DIMV) {
        int k = idx >> 7, n = idx & 127;
        float v = W[idx];
        float h = tf32_rna(v);
        WTh[(size_t)n * HH + k] = h;
        WTl[(size_t)n * HH + k] = tf32_rna(v - h);
    }
}

// ---------------------------------------------------------------------------
// Projection via 3xTF32 mma.sync + row L2-normalize + hi/lo split output.
// 258 blocks x 256 threads. Block = 128 rows x 128 cols, K=768 in 24 k32
// chunks. Warps 4x2 (wm,wn): warp tile 32m x 64n -> 2 m-tiles x 8 n-tiles.
// X split to tf32 hi/lo on the fly into smem; W pre-split (g_WT*).
// ---------------------------------------------------------------------------
__global__ __launch_bounds__(256) void proj_kernel(
    const float* __restrict__ Qx, const float* __restrict__ Dx,
    const float* __restrict__ WTh, const float* __restrict__ WTl,
    float* __restrict__ Qh, float* __restrict__ Ql,
    float* __restrict__ Dh, float* __restrict__ Dl)
{
    extern __shared__ __align__(16) float smem[];
    float* Ash = smem;                 // [128][36]
    float* Asl = Ash + 128 * PS;
    float* Bsh = Asl + 128 * PS;       // [128][36]
    float* Bsl = Bsh + 128 * PS;
    float* ssb = Bsl + 128 * PS;       // [128][2]

    const int bx = blockIdx.x;
    const bool isQ = bx < 8;
    const float* X = isQ ? Qx : Dx;
    float* Yh = isQ ? Qh : Dh;
    float* Yl = isQ ? Ql : Dl;
    const size_t row0 = isQ ? (size_t)bx * 128 : (size_t)(bx - 8) * 128;

    const int tid  = threadIdx.x;
    const int warp = tid >> 5, lane = tid & 31;
    const int wm = warp >> 1, wn = warp & 1;
    const int g = lane >> 2, t = lane & 3;

    float C[2][8][4];
#pragma unroll
    for (int mt = 0; mt < 2; mt++)
#pragma unroll
        for (int nt = 0; nt < 8; nt++)
#pragma unroll
            for (int i = 0; i < 4; i++) C[mt][nt][i] = 0.0f;

    for (int c = 0; c < 24; c++) {
        const int k0 = c * 32;
        // Stage X chunk (128 x 32), splitting fp32 -> tf32 hi/lo.
#pragma unroll
        for (int it = 0; it < 4; it++) {
            int idx = tid + 256 * it;            // 0..1023
            int r = idx >> 3, j = idx & 7;
            float4 v = *(const float4*)&X[(row0 + r) * HH + k0 + 4 * j];
            float4 h, l;
            h.x = tf32_rna(v.x); l.x = tf32_rna(v.x - h.x);
            h.y = tf32_rna(v.y); l.y = tf32_rna(v.y - h.y);
            h.z = tf32_rna(v.z); l.z = tf32_rna(v.z - h.z);
            h.w = tf32_rna(v.w); l.w = tf32_rna(v.w - h.w);
            *(float4*)&Ash[r * PS + 4 * j] = h;
            *(float4*)&Asl[r * PS + 4 * j] = l;
        }
        // Stage W chunk (pre-split, k-major): coalesced float4.
#pragma unroll
        for (int it = 0; it < 4; it++) {
            int idx = tid + 256 * it;
            int n = idx >> 3, j = idx & 7;
            *(float4*)&Bsh[n * PS + 4 * j] =
                *(const float4*)&WTh[(size_t)n * HH + k0 + 4 * j];
            *(float4*)&Bsl[n * PS + 4 * j] =
                *(const float4*)&WTl[(size_t)n * HH + k0 + 4 * j];
        }
        __syncthreads();

#pragma unroll
        for (int ks = 0; ks < 4; ks++) {
            const int kk = ks * 8;
            uint32_t Ah[2][4], Al[2][4], Bh[8][2], Bl[8][2];
#pragma unroll
            for (int mt = 0; mt < 2; mt++) {
                int rb = wm * 32 + mt * 16;
                Ah[mt][0] = B32(Ash[(rb + g) * PS + kk + t]);
                Ah[mt][1] = B32(Ash[(rb + g + 8) * PS + kk + t]);
                Ah[mt][2] = B32(Ash[(rb + g) * PS + kk + t + 4]);
                Ah[mt][3] = B32(Ash[(rb + g + 8) * PS + kk + t + 4]);
                Al[mt][0] = B32(Asl[(rb + g) * PS + kk + t]);
                Al[mt][1] = B32(Asl[(rb + g + 8) * PS + kk + t]);
                Al[mt][2] = B32(Asl[(rb + g) * PS + kk + t + 4]);
                Al[mt][3] = B32(Asl[(rb + g + 8) * PS + kk + t + 4]);
            }
#pragma unroll
            for (int nt = 0; nt < 8; nt++) {
                int nb = wn * 64 + nt * 8 + g;
                Bh[nt][0] = B32(Bsh[nb * PS + kk + t]);
                Bh[nt][1] = B32(Bsh[nb * PS + kk + t + 4]);
                Bl[nt][0] = B32(Bsl[nb * PS + kk + t]);
                Bl[nt][1] = B32(Bsl[nb * PS + kk + t + 4]);
            }
#pragma unroll
            for (int mt = 0; mt < 2; mt++)
#pragma unroll
                for (int nt = 0; nt < 8; nt++) {
                    mma_tf32(C[mt][nt], Ah[mt], Bh[nt]);   // hi*hi
                    mma_tf32(C[mt][nt], Al[mt], Bh[nt]);   // lo*hi
                    mma_tf32(C[mt][nt], Ah[mt], Bl[nt]);   // hi*lo
                }
        }
        __syncthreads();
    }

    // Row sum-of-squares: row's 128 cols span wn(2) x t(4) x nt(8) x 2.
#pragma unroll
    for (int mt = 0; mt < 2; mt++) {
        float s0 = 0.0f, s1 = 0.0f;
#pragma unroll
        for (int nt = 0; nt < 8; nt++) {
            s0 += C[mt][nt][0] * C[mt][nt][0] + C[mt][nt][1] * C[mt][nt][1];
            s1 += C[mt][nt][2] * C[mt][nt][2] + C[mt][nt][3] * C[mt][nt][3];
        }
#pragma unroll
        for (int off = 1; off <= 2; off <<= 1) {
            s0 += __shfl_xor_sync(0xffffffffu, s0, off);   // reduce over t
            s1 += __shfl_xor_sync(0xffffffffu, s1, off);
        }
        if (t == 0) {
            ssb[(wm * 32 + mt * 16 + g) * 2 + wn] = s0;
            ssb[(wm * 32 + mt * 16 + g + 8) * 2 + wn] = s1;
        }
    }
    __syncthreads();

#pragma unroll
    for (int mt = 0; mt < 2; mt++) {
        int ra = wm * 32 + mt * 16 + g, rb = ra + 8;
        float ia = 1.0f / fmaxf(sqrtf(ssb[ra * 2] + ssb[ra * 2 + 1]), 1e-12f);
        float ib = 1.0f / fmaxf(sqrtf(ssb[rb * 2] + ssb[rb * 2 + 1]), 1e-12f);
#pragma unroll
        for (int nt = 0; nt < 8; nt++) {
            int col = wn * 64 + nt * 8 + 2 * t;
            float v0 = C[mt][nt][0] * ia, v1 = C[mt][nt][1] * ia;
            float v2 = C[mt][nt][2] * ib, v3 = C[mt][nt][3] * ib;
            float h0 = tf32_rna(v0), h1 = tf32_rna(v1);
            float h2 = tf32_rna(v2), h3 = tf32_rna(v3);
            size_t ba = (row0 + ra) * DIMV + col;
            size_t bb = (row0 + rb) * DIMV + col;
            *(float2*)&Yh[ba] = make_float2(h0, h1);
            *(float2*)&Yl[ba] = make_float2(tf32_rna(v0 - h0), tf32_rna(v1 - h1));
            *(float2*)&Yh[bb] = make_float2(h2, h3);
            *(float2*)&Yl[bb] = make_float2(tf32_rna(v2 - h2), tf32_rna(v3 - h3));
        }
    }
}

// ---------------------------------------------------------------------------
// Fused scoring via 3xTF32 mma.sync. Block = (4q, 1d): M=128 (4q x 32m),
// N=160, K=128 in four k32 chunks. 1600 blocks x 256 threads.
// Warps 4x2 (wm=q index, wn): warp tile 32m x 80n -> 2 m-tiles x 10 n-tiles.
// Epilogue: masked gumbel argmax per m-row + qmask-weighted sum.
// ---------------------------------------------------------------------------
__global__ __launch_bounds__(256) void score_kernel(
    const float* __restrict__ gumbel,
    const float* __restrict__ q_mask,
    const float* __restrict__ d_mask,
    float* __restrict__ out)
{
    extern __shared__ __align__(16) float smem[];
    float* Ash = smem;                      // [128][36]
    float* Asl = Ash + 128 * PS;
    float* Bsh = Asl + 128 * PS;            // [160][36]
    float* Bsl = Bsh + 160 * PS;
    float* dmask_s = Bsl + 160 * PS;        // [160]
    float* qmask_s = dmask_s + NN;          // [128]
    float* zbuf = qmask_s + 128;            // [128][2]
    float* sbuf = zbuf + 256;               // [128][2]

    const int bx = blockIdx.x;
    const int d  = bx % ND_;
    const int qg = bx / ND_;                // 0..7
    const int tid  = threadIdx.x;
    const int warp = tid >> 5, lane = tid & 31;
    const int wm = warp >> 1, wn = warp & 1;
    const int g = lane >> 2, t = lane & 3;

    if (tid < NN)  dmask_s[tid] = d_mask[(size_t)d * NN + tid];
    if (tid < 128) qmask_s[tid] = q_mask[(size_t)qg * 128 + tid];

    float C[2][10][4];
#pragma unroll
    for (int mt = 0; mt < 2; mt++)
#pragma unroll
        for (int nt = 0; nt < 10; nt++)
#pragma unroll
            for (int i = 0; i < 4; i++) C[mt][nt][i] = 0.0f;

    for (int c = 0; c < 4; c++) {
        const int k0 = c * 32;
        // Stage A (Qp hi/lo): 128 x 32 = 1024 float4 each, coalesced.
#pragma unroll
        for (int it = 0; it < 4; it++) {
            int idx = tid + 256 * it;
            int r = idx >> 3, j = idx & 7;
            size_t src = (size_t)(qg * 128 + r) * DIMV + k0 + 4 * j;
            *(float4*)&Ash[r * PS + 4 * j] = *(const float4*)&g_Qh[src];
            *(float4*)&Asl[r * PS + 4 * j] = *(const float4*)&g_Ql[src];
        }
        // Stage B (Dp hi/lo): 160 x 32 = 1280 float4 each (L2-resident).
#pragma unroll
        for (int it = 0; it < 5; it++) {
            int idx = tid + 256 * it;
            int n = idx >> 3, j = idx & 7;
            size_t src = (size_t)(d * NN + n) * DIMV + k0 + 4 * j;
            *(float4*)&Bsh[n * PS + 4 * j] = *(const float4*)&g_Dh[src];
            *(float4*)&Bsl[n * PS + 4 * j] = *(const float4*)&g_Dl[src];
        }
        __syncthreads();

#pragma unroll
        for (int ks = 0; ks < 4; ks++) {
            const int kk = ks * 8;
            uint32_t Ah[2][4], Al[2][4], Bh[10][2], Bl[10][2];
#pragma unroll
            for (int mt = 0; mt < 2; mt++) {
                int rb = wm * 32 + mt * 16;
                Ah[mt][0] = B32(Ash[(rb + g) * PS + kk + t]);
                Ah[mt][1] = B32(Ash[(rb + g + 8) * PS + kk + t]);
                Ah[mt][2] = B32(Ash[(rb + g) * PS + kk + t + 4]);
                Ah[mt][3] = B32(Ash[(rb + g + 8) * PS + kk + t + 4]);
                Al[mt][0] = B32(Asl[(rb + g) * PS + kk + t]);
                Al[mt][1] = B32(Asl[(rb + g + 8) * PS + kk + t]);
                Al[mt][2] = B32(Asl[(rb + g) * PS + kk + t + 4]);
                Al[mt][3] = B32(Asl[(rb + g + 8) * PS + kk + t + 4]);
            }
#pragma unroll
            for (int nt = 0; nt < 10; nt++) {
                int nb = wn * 80 + nt * 8 + g;
                Bh[nt][0] = B32(Bsh[nb * PS + kk + t]);
                Bh[nt][1] = B32(Bsh[nb * PS + kk + t + 4]);
                Bl[nt][0] = B32(Bsl[nb * PS + kk + t]);
                Bl[nt][1] = B32(Bsl[nb * PS + kk + t + 4]);
            }
#pragma unroll
            for (int mt = 0; mt < 2; mt++)
#pragma unroll
                for (int nt = 0; nt < 10; nt++) {
                    mma_tf32(C[mt][nt], Ah[mt], Bh[nt]);   // hi*hi
                    mma_tf32(C[mt][nt], Al[mt], Bh[nt]);   // lo*hi
                    mma_tf32(C[mt][nt], Ah[mt], Bl[nt]);   // hi*lo
                }
        }
        __syncthreads();
    }

    // Epilogue: per m-row masked gumbel-argmax over this warp's 80 n.
#pragma unroll
    for (int mt = 0; mt < 2; mt++) {
#pragma unroll
        for (int h = 0; h < 2; h++) {
            const int r = wm * 32 + mt * 16 + g + h * 8;   // local row 0..127
            const int m = r & 31;
            const float* grow = gumbel +
                (((size_t)(qg * 4 + wm) * ND_ + d) * MM + m) * NN;
            float bz = -3.0e38f, bs = 0.0f;
#pragma unroll
            for (int nt = 0; nt < 10; nt++) {
                const int n = wn * 80 + nt * 8 + 2 * t;
                float2 dm = *(const float2*)&dmask_s[n];
                float2 gv = *(const float2*)&grow[n];
                float c0 = C[mt][nt][2 * h], c1 = C[mt][nt][2 * h + 1];
                float s0 = c0 * dm.x + (1.0f - dm.x) * NEGV;  // exact select
                float s1 = c1 * dm.y + (1.0f - dm.y) * NEGV;
                float z0 = s0 * 10.0f + gv.x;                 // TEMP=0.1
                float z1 = s1 * 10.0f + gv.y;
                if (z0 > bz) { bz = z0; bs = s0; }
                if (z1 > bz) { bz = z1; bs = s1; }
            }
#pragma unroll
            for (int off = 1; off <= 2; off <<= 1) {          // reduce over t
                float zo = __shfl_xor_sync(0xffffffffu, bz, off);
                float so = __shfl_xor_sync(0xffffffffu, bs, off);
                if (zo > bz) { bz = zo; bs = so; }
            }
            if (t == 0) { zbuf[r * 2 + wn] = bz; sbuf[r * 2 + wn] = bs; }
        }
    }
    __syncthreads();

    if (tid < 128) {
        const int r = tid;
        float z0 = zbuf[2 * r], z1 = zbuf[2 * r + 1];
        float s  = (z1 > z0) ? sbuf[2 * r + 1] : sbuf[2 * r];
        float p  = qmask_s[r] * s;
#pragma unroll
        for (int off = 16; off >= 1; off >>= 1)
            p += __shfl_xor_sync(0xffffffffu, p, off);        // sum over m
        if ((r & 31) == 0)
            out[(size_t)(qg * 4 + (r >> 5)) * ND_ + d] = p;
    }
}

// ---------------------------------------------------------------------------
extern "C" void kernel_launch(void* const* d_in, const int* in_sizes, int n_in,
                              void* d_out, int out_size)
{
    const float* Q      = (const float*)d_in[0];  // (32,32,768)
    const float* D      = (const float*)d_in[1];  // (200,160,768)
    const float* q_mask = (const float*)d_in[2];  // (32,32)
    const float* d_mask = (const float*)d_in[3];  // (200,160)
    const float* gumbel = (const float*)d_in[4];  // (32,200,32,160)
    const float* W      = (const float*)d_in[5];  // (768,128)
    float* out = (float*)d_out;                   // (32,200)

    float *Qh, *Ql, *Dh, *Dl, *WTh, *WTl;
    cudaGetSymbolAddress((void**)&Qh,  g_Qh);
    cudaGetSymbolAddress((void**)&Ql,  g_Ql);
    cudaGetSymbolAddress((void**)&Dh,  g_Dh);
    cudaGetSymbolAddress((void**)&Dl,  g_Dl);
    cudaGetSymbolAddress((void**)&WTh, g_WTh);
    cudaGetSymbolAddress((void**)&WTl, g_WTl);

    // 1) Split + transpose W (tiny).
    wsplit_kernel<<<(HH * DIMV + 255) / 256, 256>>>(W, WTh, WTl);

    // 2) Projection (8 Q-blocks + 250 D-blocks of 128 rows).
    const int proj_smem = (4 * 128 * PS + 256) * sizeof(float);
    cudaFuncSetAttribute(proj_kernel,
                         cudaFuncAttributeMaxDynamicSharedMemorySize, proj_smem);
    proj_kernel<<<258, 256, proj_smem>>>(Q, D, WTh, WTl, Qh, Ql, Dh, Dl);

    // 3) Fused sim + gumbel-argmax + score.
    const int score_smem =
        (2 * 128 * PS + 2 * 160 * PS + NN + 128 + 512) * sizeof(float);
    cudaFuncSetAttribute(score_kernel,
                         cudaFuncAttributeMaxDynamicSharedMemorySize, score_smem);
    score_kernel<<<(NQ / 4) * ND_, 256, score_smem>>>(gumbel, q_mask, d_mask, out);
}

// round 16
// speedup vs baseline: 1.7034x; 1.0473x over previous
#include <cuda_runtime.h>
#include <math.h>
#include <stdint.h>

#define NQ   32
#define MM   32
#define ND_  200
#define NN   160
#define HH   768
#define DIMV 128
#define NEGV (-10000.0f)

// ---------------------------------------------------------------------------
// Scratch (no cudaMalloc allowed): tf32 hi/lo splits.
// ---------------------------------------------------------------------------
__device__ float g_Qh[NQ * MM * DIMV];     // [m_global][k] row-major
__device__ float g_Ql[NQ * MM * DIMV];
__device__ float g_Dh[ND_ * NN * DIMV];    // [d*160+n][k]
__device__ float g_Dl[ND_ * NN * DIMV];
__device__ float g_WTh[DIMV * HH];         // W transposed: [n][k], tf32 hi
__device__ float g_WTl[DIMV * HH];         // lo

__device__ __forceinline__ uint32_t smem_u32(const void* p) {
    uint32_t a;
    asm("{ .reg .u64 t; cvta.to.shared.u64 t, %1; cvt.u32.u64 %0, t; }"
        : "=r"(a) : "l"(p));
    return a;
}
__device__ __forceinline__ float tf32_rna(float x) {
    uint32_t u;
    asm("cvt.rna.tf32.f32 %0, %1;" : "=r"(u) : "f"(x));
    return __uint_as_float(u);
}
// 16B async copy gmem->smem (sm_80+ baseline; LDGSTS in SASS).
__device__ __forceinline__ void cp16(uint32_t dst, const void* src) {
    asm volatile("cp.async.cg.shared.global [%0], [%1], 16;"
                 :: "r"(dst), "l"(src) : "memory");
}
#define CP_COMMIT() asm volatile("cp.async.commit_group;" ::: "memory")
#define CP_WAIT0()  asm volatile("cp.async.wait_group 0;" ::: "memory")

// Warp-level tensor-core MMA (sm_80+ baseline PTX -> works on compute_103):
// C[16x8] += A[16x8] * B[8x8], A row-major, B col-major ([n][k]), tf32 in.
__device__ __forceinline__ void mma_tf32(float* c, const uint32_t* a,
                                         const uint32_t* b) {
    asm("mma.sync.aligned.m16n8k8.row.col.f32.tf32.tf32.f32 "
        "{%0,%1,%2,%3}, {%4,%5,%6,%7}, {%8,%9}, {%0,%1,%2,%3};"
        : "+f"(c[0]), "+f"(c[1]), "+f"(c[2]), "+f"(c[3])
        : "r"(a[0]), "r"(a[1]), "r"(a[2]), "r"(a[3]), "r"(b[0]), "r"(b[1]));
}

#define B32(x) __float_as_uint(x)
#define PS 36   // k-chunk smem row stride: 36 mod 32 = 4 -> fragment LDS
                // addrs (4g + t) form a bank permutation: conflict-free.

// ---------------------------------------------------------------------------
// Prep: split + transpose W once.
// ---------------------------------------------------------------------------
__global__ void wsplit_kernel(const float* __restrict__ W,
                              float* __restrict__ WTh, float* __restrict__ WTl)
{
    int idx = blockIdx.x * 256 + threadIdx.x;
    if (idx < HH * DIMV) {
        int k = idx >> 7, n = idx & 127;
        float v = W[idx];
        float h = tf32_rna(v);
        WTh[(size_t)n * HH + k] = h;
        WTl[(size_t)n * HH + k] = tf32_rna(v - h);
    }
}

// ---------------------------------------------------------------------------
// Projection via 3xTF32 mma.sync, cp.async double-buffered W + register-
// prefetched X. 258 blocks x 256 threads; block = 128 rows x 128 cols,
// K=768 in 24 k32 chunks. Warps 4x2; warp tile 32m x 64n (2 mt x 8 nt).
// smem (floats): stA0(9216=Ash+Asl) stA1 stW0(9216) stW1 ssb(256) = 148.5KB
// ---------------------------------------------------------------------------
__global__ __launch_bounds__(256) void proj_kernel(
    const float* __restrict__ Qx, const float* __restrict__ Dx,
    const float* __restrict__ WTh, const float* __restrict__ WTl,
    float* __restrict__ Qh, float* __restrict__ Ql,
    float* __restrict__ Dh, float* __restrict__ Dl)
{
    extern __shared__ __align__(16) float smem[];
    float* ssb = smem + 36864;                 // [128][2]

    const int bx = blockIdx.x;
    const bool isQ = bx < 8;
    const float* X = isQ ? Qx : Dx;
    float* Yh = isQ ? Qh : Dh;
    float* Yl = isQ ? Ql : Dl;
    const size_t row0 = isQ ? (size_t)bx * 128 : (size_t)(bx - 8) * 128;

    const int tid  = threadIdx.x;
    const int warp = tid >> 5, lane = tid & 31;
    const int wm = warp >> 1, wn = warp & 1;
    const int g = lane >> 2, t = lane & 3;
    const uint32_t sbase = smem_u32(smem);

    float C[2][8][4];
#pragma unroll
    for (int mt = 0; mt < 2; mt++)
#pragma unroll
        for (int nt = 0; nt < 8; nt++)
#pragma unroll
            for (int i = 0; i < 4; i++) C[mt][nt][i] = 0.0f;

    // X prefetch registers (one chunk ahead) + W cp.async prologue.
    float4 xr[4];
#pragma unroll
    for (int it = 0; it < 4; it++) {
        int idx = tid + 256 * it;
        int r = idx >> 3, j = idx & 7;
        xr[it] = *(const float4*)&X[(row0 + r) * HH + 4 * j];
    }
    {
        uint32_t wb = sbase + (18432 + 0 * 9216) * 4;
#pragma unroll
        for (int it = 0; it < 4; it++) {
            int idx = tid + 256 * it;
            int n = idx >> 3, j = idx & 7;
            uint32_t dst = wb + (n * PS + 4 * j) * 4;
            cp16(dst,            &WTh[(size_t)n * HH + 4 * j]);
            cp16(dst + 4608 * 4, &WTl[(size_t)n * HH + 4 * j]);
        }
    }
    CP_COMMIT();

    for (int c = 0; c < 24; c++) {
        const int buf = c & 1;
        CP_WAIT0();
        __syncthreads();        // W(c) visible; buffers for this iter free

        // STS-split this chunk's X from registers.
        {
            float* Ah = smem + buf * 9216;
            float* Al = Ah + 4608;
#pragma unroll
            for (int it = 0; it < 4; it++) {
                int idx = tid + 256 * it;
                int r = idx >> 3, j = idx & 7;
                float4 v = xr[it], h, l;
                h.x = tf32_rna(v.x); l.x = tf32_rna(v.x - h.x);
                h.y = tf32_rna(v.y); l.y = tf32_rna(v.y - h.y);
                h.z = tf32_rna(v.z); l.z = tf32_rna(v.z - h.z);
                h.w = tf32_rna(v.w); l.w = tf32_rna(v.w - h.w);
                *(float4*)&Ah[r * PS + 4 * j] = h;
                *(float4*)&Al[r * PS + 4 * j] = l;
            }
        }
        // Prefetch next chunk (X->regs, W->other smem buffer).
        if (c < 23) {
            const int k0n = (c + 1) * 32;
#pragma unroll
            for (int it = 0; it < 4; it++) {
                int idx = tid + 256 * it;
                int r = idx >> 3, j = idx & 7;
                xr[it] = *(const float4*)&X[(row0 + r) * HH + k0n + 4 * j];
            }
            uint32_t wb = sbase + (18432 + ((c + 1) & 1) * 9216) * 4;
#pragma unroll
            for (int it = 0; it < 4; it++) {
                int idx = tid + 256 * it;
                int n = idx >> 3, j = idx & 7;
                uint32_t dst = wb + (n * PS + 4 * j) * 4;
                cp16(dst,            &WTh[(size_t)n * HH + k0n + 4 * j]);
                cp16(dst + 4608 * 4, &WTl[(size_t)n * HH + k0n + 4 * j]);
            }
            CP_COMMIT();
        }
        __syncthreads();        // A staging visible to all warps

        const float* Ash = smem + buf * 9216;
        const float* Asl = Ash + 4608;
        const float* Bsh = smem + 18432 + buf * 9216;
        const float* Bsl = Bsh + 4608;

#pragma unroll
        for (int ks = 0; ks < 4; ks++) {
            const int kk = ks * 8;
            uint32_t Ah[2][4], Al[2][4], Bh[8][2], Bl[8][2];
#pragma unroll
            for (int mt = 0; mt < 2; mt++) {
                int rb = wm * 32 + mt * 16;
                Ah[mt][0] = B32(Ash[(rb + g) * PS + kk + t]);
                Ah[mt][1] = B32(Ash[(rb + g + 8) * PS + kk + t]);
                Ah[mt][2] = B32(Ash[(rb + g) * PS + kk + t + 4]);
                Ah[mt][3] = B32(Ash[(rb + g + 8) * PS + kk + t + 4]);
                Al[mt][0] = B32(Asl[(rb + g) * PS + kk + t]);
                Al[mt][1] = B32(Asl[(rb + g + 8) * PS + kk + t]);
                Al[mt][2] = B32(Asl[(rb + g) * PS + kk + t + 4]);
                Al[mt][3] = B32(Asl[(rb + g + 8) * PS + kk + t + 4]);
            }
#pragma unroll
            for (int nt = 0; nt < 8; nt++) {
                int nb = wn * 64 + nt * 8 + g;
                Bh[nt][0] = B32(Bsh[nb * PS + kk + t]);
                Bh[nt][1] = B32(Bsh[nb * PS + kk + t + 4]);
                Bl[nt][0] = B32(Bsl[nb * PS + kk + t]);
                Bl[nt][1] = B32(Bsl[nb * PS + kk + t + 4]);
            }
#pragma unroll
            for (int mt = 0; mt < 2; mt++)
#pragma unroll
                for (int nt = 0; nt < 8; nt++) {
                    mma_tf32(C[mt][nt], Ah[mt], Bh[nt]);   // hi*hi
                    mma_tf32(C[mt][nt], Al[mt], Bh[nt]);   // lo*hi
                    mma_tf32(C[mt][nt], Ah[mt], Bl[nt]);   // hi*lo
                }
        }
    }
    __syncthreads();

    // Row sum-of-squares + normalize + hi/lo split output (as R12).
#pragma unroll
    for (int mt = 0; mt < 2; mt++) {
        float s0 = 0.0f, s1 = 0.0f;
#pragma unroll
        for (int nt = 0; nt < 8; nt++) {
            s0 += C[mt][nt][0] * C[mt][nt][0] + C[mt][nt][1] * C[mt][nt][1];
            s1 += C[mt][nt][2] * C[mt][nt][2] + C[mt][nt][3] * C[mt][nt][3];
        }
#pragma unroll
        for (int off = 1; off <= 2; off <<= 1) {
            s0 += __shfl_xor_sync(0xffffffffu, s0, off);
            s1 += __shfl_xor_sync(0xffffffffu, s1, off);
        }
        if (t == 0) {
            ssb[(wm * 32 + mt * 16 + g) * 2 + wn] = s0;
            ssb[(wm * 32 + mt * 16 + g + 8) * 2 + wn] = s1;
        }
    }
    __syncthreads();

#pragma unroll
    for (int mt = 0; mt < 2; mt++) {
        int ra = wm * 32 + mt * 16 + g, rb = ra + 8;
        float ia = 1.0f / fmaxf(sqrtf(ssb[ra * 2] + ssb[ra * 2 + 1]), 1e-12f);
        float ib = 1.0f / fmaxf(sqrtf(ssb[rb * 2] + ssb[rb * 2 + 1]), 1e-12f);
#pragma unroll
        for (int nt = 0; nt < 8; nt++) {
            int col = wn * 64 + nt * 8 + 2 * t;
            float v0 = C[mt][nt][0] * ia, v1 = C[mt][nt][1] * ia;
            float v2 = C[mt][nt][2] * ib, v3 = C[mt][nt][3] * ib;
            float h0 = tf32_rna(v0), h1 = tf32_rna(v1);
            float h2 = tf32_rna(v2), h3 = tf32_rna(v3);
            size_t ba = (row0 + ra) * DIMV + col;
            size_t bb = (row0 + rb) * DIMV + col;
            *(float2*)&Yh[ba] = make_float2(h0, h1);
            *(float2*)&Yl[ba] = make_float2(tf32_rna(v0 - h0), tf32_rna(v1 - h1));
            *(float2*)&Yh[bb] = make_float2(h2, h3);
            *(float2*)&Yl[bb] = make_float2(tf32_rna(v2 - h2), tf32_rna(v3 - h3));
        }
    }
}

// ---------------------------------------------------------------------------
// Fused scoring via 3xTF32 mma.sync, fully cp.async double-buffered; gumbel
// prefetched into smem (overlaying stage 0) during the last chunk's MMAs.
// Block = (4q, 1d): M=128, N=160, K=128 in four k32 chunks. 1600 x 256.
// smem (floats): st0(20736: Ash 4608|Asl 4608|Bsh 5760|Bsl 5760) st1(20736)
//                dmask(160) qmask(128) zbuf(256) sbuf(256)  = 169,088 B
// ---------------------------------------------------------------------------
__global__ __launch_bounds__(256) void score_kernel(
    const float* __restrict__ gumbel,
    const float* __restrict__ q_mask,
    const float* __restrict__ d_mask,
    float* __restrict__ out)
{
    extern __shared__ __align__(16) float smem[];
    float* dmask_s = smem + 41472;          // [160]
    float* qmask_s = dmask_s + NN;          // [128]
    float* zbuf    = qmask_s + 128;         // [128][2]
    float* sbuf    = zbuf + 256;            // [128][2]
    float* gum_s   = smem;                  // overlays stage 0 (20480<=20736)

    const int bx = blockIdx.x;
    const int d  = bx % ND_;
    const int qg = bx / ND_;                // 0..7
    const int tid  = threadIdx.x;
    const int warp = tid >> 5, lane = tid & 31;
    const int wm = warp >> 1, wn = warp & 1;
    const int g = lane >> 2, t = lane & 3;
    const uint32_t sbase = smem_u32(smem);

    if (tid < NN)  dmask_s[tid] = d_mask[(size_t)d * NN + tid];
    if (tid < 128) qmask_s[tid] = q_mask[(size_t)qg * 128 + tid];

    float C[2][10][4];
#pragma unroll
    for (int mt = 0; mt < 2; mt++)
#pragma unroll
        for (int nt = 0; nt < 10; nt++)
#pragma unroll
            for (int i = 0; i < 4; i++) C[mt][nt][i] = 0.0f;

    const float4* Qh4 = (const float4*)g_Qh;
    const float4* Ql4 = (const float4*)g_Ql;
    const float4* Dh4 = (const float4*)g_Dh;
    const float4* Dl4 = (const float4*)g_Dl;

    // ---- prologue: stage chunk 0 into buffer 0 ----
    {
        uint32_t bb = sbase;
#pragma unroll
        for (int it = 0; it < 4; it++) {
            int idx = tid + 256 * it;
            int r = idx >> 3, j = idx & 7;
            uint32_t dst = bb + (r * PS + 4 * j) * 4;
            size_t src = (size_t)(qg * 128 + r) * 32 + j;
            cp16(dst,            Qh4 + src);
            cp16(dst + 4608 * 4, Ql4 + src);
        }
#pragma unroll
        for (int it = 0; it < 5; it++) {
            int idx = tid + 256 * it;
            int n = idx >> 3, j = idx & 7;
            uint32_t dst = bb + (9216 + n * PS + 4 * j) * 4;
            size_t src = (size_t)(d * NN + n) * 32 + j;
            cp16(dst,            Dh4 + src);
            cp16(dst + 5760 * 4, Dl4 + src);
        }
    }
    CP_COMMIT();

    for (int c = 0; c < 4; c++) {
        const int buf = c & 1;
        CP_WAIT0();
        __syncthreads();        // chunk c visible; other buffer free

        if (c < 3) {            // prefetch chunk c+1 into the other buffer
            uint32_t bb = sbase + ((c + 1) & 1) * 20736 * 4;
            const int kof = (c + 1) * 8;
#pragma unroll
            for (int it = 0; it < 4; it++) {
                int idx = tid + 256 * it;
                int r = idx >> 3, j = idx & 7;
                uint32_t dst = bb + (r * PS + 4 * j) * 4;
                size_t src = (size_t)(qg * 128 + r) * 32 + kof + j;
                cp16(dst,            Qh4 + src);
                cp16(dst + 4608 * 4, Ql4 + src);
            }
#pragma unroll
            for (int it = 0; it < 5; it++) {
                int idx = tid + 256 * it;
                int n = idx >> 3, j = idx & 7;
                uint32_t dst = bb + (9216 + n * PS + 4 * j) * 4;
                size_t src = (size_t)(d * NN + n) * 32 + kof + j;
                cp16(dst,            Dh4 + src);
                cp16(dst + 5760 * 4, Dl4 + src);
            }
        } else {                // prefetch gumbel into stage 0 (now free)
#pragma unroll
            for (int it = 0; it < 20; it++) {
                int idx = tid + 256 * it;          // 0..5119 float4s
                int r = idx / 40, j = idx - r * 40;
                int q = qg * 4 + (r >> 5), m = r & 31;
                const float4* src = (const float4*)gumbel +
                    (((size_t)q * ND_ + d) * MM + m) * 40 + j;
                cp16(sbase + (r * 160 + 4 * j) * 4, src);
            }
        }
        CP_COMMIT();

        const float* Ash = smem + buf * 20736;
        const float* Asl = Ash + 4608;
        const float* Bsh = Ash + 9216;
        const float* Bsl = Ash + 14976;

#pragma unroll
        for (int ks = 0; ks < 4; ks++) {
            const int kk = ks * 8;
            uint32_t Ah[2][4], Al[2][4], Bh[10][2], Bl[10][2];
#pragma unroll
            for (int mt = 0; mt < 2; mt++) {
                int rb = wm * 32 + mt * 16;
                Ah[mt][0] = B32(Ash[(rb + g) * PS + kk + t]);
                Ah[mt][1] = B32(Ash[(rb + g + 8) * PS + kk + t]);
                Ah[mt][2] = B32(Ash[(rb + g) * PS + kk + t + 4]);
                Ah[mt][3] = B32(Ash[(rb + g + 8) * PS + kk + t + 4]);
                Al[mt][0] = B32(Asl[(rb + g) * PS + kk + t]);
                Al[mt][1] = B32(Asl[(rb + g + 8) * PS + kk + t]);
                Al[mt][2] = B32(Asl[(rb + g) * PS + kk + t + 4]);
                Al[mt][3] = B32(Asl[(rb + g + 8) * PS + kk + t + 4]);
            }
#pragma unroll
            for (int nt = 0; nt < 10; nt++) {
                int nb = wn * 80 + nt * 8 + g;
                Bh[nt][0] = B32(Bsh[nb * PS + kk + t]);
                Bh[nt][1] = B32(Bsh[nb * PS + kk + t + 4]);
                Bl[nt][0] = B32(Bsl[nb * PS + kk + t]);
                Bl[nt][1] = B32(Bsl[nb * PS + kk + t + 4]);
            }
#pragma unroll
            for (int mt = 0; mt < 2; mt++)
#pragma unroll
                for (int nt = 0; nt < 10; nt++) {
                    mma_tf32(C[mt][nt], Ah[mt], Bh[nt]);   // hi*hi
                    mma_tf32(C[mt][nt], Al[mt], Bh[nt]);   // lo*hi
                    mma_tf32(C[mt][nt], Ah[mt], Bl[nt]);   // hi*lo
                }
        }
    }

    CP_WAIT0();
    __syncthreads();            // gumbel in smem

    // Epilogue: per m-row masked gumbel-argmax over this warp's 80 n.
#pragma unroll
    for (int mt = 0; mt < 2; mt++) {
#pragma unroll
        for (int h = 0; h < 2; h++) {
            const int r = wm * 32 + mt * 16 + g + h * 8;   // local row 0..127
            const float* grow = gum_s + r * 160;
            float bz = -3.0e38f, bs = 0.0f;
#pragma unroll
            for (int nt = 0; nt < 10; nt++) {
                const int n = wn * 80 + nt * 8 + 2 * t;
                float2 dm = *(const float2*)&dmask_s[n];
                float2 gv = *(const float2*)&grow[n];
                float c0 = C[mt][nt][2 * h], c1 = C[mt][nt][2 * h + 1];
                float s0 = c0 * dm.x + (1.0f - dm.x) * NEGV;  // exact select
                float s1 = c1 * dm.y + (1.0f - dm.y) * NEGV;
                float z0 = s0 * 10.0f + gv.x;                 // TEMP=0.1
                float z1 = s1 * 10.0f + gv.y;
                if (z0 > bz) { bz = z0; bs = s0; }
                if (z1 > bz) { bz = z1; bs = s1; }
            }
#pragma unroll
            for (int off = 1; off <= 2; off <<= 1) {          // reduce over t
                float zo = __shfl_xor_sync(0xffffffffu, bz, off);
                float so = __shfl_xor_sync(0xffffffffu, bs, off);
                if (zo > bz) { bz = zo; bs = so; }
            }
            if (t == 0) { zbuf[r * 2 + wn] = bz; sbuf[r * 2 + wn] = bs; }
        }
    }
    __syncthreads();

    if (tid < 128) {
        const int r = tid;
        float z0 = zbuf[2 * r], z1 = zbuf[2 * r + 1];
        float s  = (z1 > z0) ? sbuf[2 * r + 1] : sbuf[2 * r];
        float p  = qmask_s[r] * s;
#pragma unroll
        for (int off = 16; off >= 1; off >>= 1)
            p += __shfl_xor_sync(0xffffffffu, p, off);        // sum over m
        if ((r & 31) == 0)
            out[(size_t)(qg * 4 + (r >> 5)) * ND_ + d] = p;
    }
}

// ---------------------------------------------------------------------------
extern "C" void kernel_launch(void* const* d_in, const int* in_sizes, int n_in,
                              void* d_out, int out_size)
{
    const float* Q      = (const float*)d_in[0];  // (32,32,768)
    const float* D      = (const float*)d_in[1];  // (200,160,768)
    const float* q_mask = (const float*)d_in[2];  // (32,32)
    const float* d_mask = (const float*)d_in[3];  // (200,160)
    const float* gumbel = (const float*)d_in[4];  // (32,200,32,160)
    const float* W      = (const float*)d_in[5];  // (768,128)
    float* out = (float*)d_out;                   // (32,200)

    float *Qh, *Ql, *Dh, *Dl, *WTh, *WTl;
    cudaGetSymbolAddress((void**)&Qh,  g_Qh);
    cudaGetSymbolAddress((void**)&Ql,  g_Ql);
    cudaGetSymbolAddress((void**)&Dh,  g_Dh);
    cudaGetSymbolAddress((void**)&Dl,  g_Dl);
    cudaGetSymbolAddress((void**)&WTh, g_WTh);
    cudaGetSymbolAddress((void**)&WTl, g_WTl);

    // 1) Split + transpose W (tiny).
    wsplit_kernel<<<(HH * DIMV + 255) / 256, 256>>>(W, WTh, WTl);

    // 2) Projection (8 Q-blocks + 250 D-blocks of 128 rows), pipelined.
    const int proj_smem = (36864 + 256) * sizeof(float);
    cudaFuncSetAttribute(proj_kernel,
                         cudaFuncAttributeMaxDynamicSharedMemorySize, proj_smem);
    proj_kernel<<<258, 256, proj_smem>>>(Q, D, WTh, WTl, Qh, Ql, Dh, Dl);

    // 3) Fused sim + gumbel-argmax + score, pipelined + gumbel prefetch.
    const int score_smem = (41472 + NN + 128 + 512) * sizeof(float);
    cudaFuncSetAttribute(score_kernel,
                         cudaFuncAttributeMaxDynamicSharedMemorySize, score_smem);
    score_kernel<<<(NQ / 4) * ND_, 256, score_smem>>>(gumbel, q_mask, d_mask, out);
}

// round 17
// speedup vs baseline: 1.9052x; 1.1185x over previous
#include <cuda_runtime.h>
#include <math.h>
#include <stdint.h>

#define NQ   32
#define MM   32
#define ND_  200
#define NN   160
#define HH   768
#define DIMV 128
#define NEGV (-10000.0f)

// ---------------------------------------------------------------------------
// Scratch: tf32 hi/lo splits in FRAGMENT-TILED layouts.
// A-frag tile (16m x 8k = 128 floats): off = lane*4 + reg,
//   lane = (m&7)*4 + (k&3), reg = ((k>>2)&1)*2 + ((m>>3)&1)
// B-frag tile (8n x 8k = 64 floats):  off = lane*2 + reg,
//   lane = (n&7)*4 + (k&3), reg = (k>>2)&1
// ---------------------------------------------------------------------------
__device__ float g_Qh[NQ * MM * DIMV];     // [64 mtile][16 ktile][128]
__device__ float g_Ql[NQ * MM * DIMV];
__device__ float g_Dh[ND_ * NN * DIMV];    // [4000 ntile][16 ktile][64]
__device__ float g_Dl[ND_ * NN * DIMV];
__device__ float g_WTh[DIMV * HH];         // [16 ntile][96 ktile][64]
__device__ float g_WTl[DIMV * HH];

__device__ __forceinline__ uint32_t smem_u32(const void* p) {
    uint32_t a;
    asm("{ .reg .u64 t; cvta.to.shared.u64 t, %1; cvt.u32.u64 %0, t; }"
        : "=r"(a) : "l"(p));
    return a;
}
__device__ __forceinline__ float tf32_rna(float x) {
    uint32_t u;
    asm("cvt.rna.tf32.f32 %0, %1;" : "=r"(u) : "f"(x));
    return __uint_as_float(u);
}
__device__ __forceinline__ void cp16(uint32_t dst, const void* src) {
    asm volatile("cp.async.cg.shared.global [%0], [%1], 16;"
                 :: "r"(dst), "l"(src) : "memory");
}
#define CP_COMMIT() asm volatile("cp.async.commit_group;" ::: "memory")
#define CP_WAIT0()  asm volatile("cp.async.wait_group 0;" ::: "memory")

__device__ __forceinline__ void mma_tf32(float* c, const uint32_t* a,
                                         const uint32_t* b) {
    asm("mma.sync.aligned.m16n8k8.row.col.f32.tf32.tf32.f32 "
        "{%0,%1,%2,%3}, {%4,%5,%6,%7}, {%8,%9}, {%0,%1,%2,%3};"
        : "+f"(c[0]), "+f"(c[1]), "+f"(c[2]), "+f"(c[3])
        : "r"(a[0]), "r"(a[1]), "r"(a[2]), "r"(a[3]), "r"(b[0]), "r"(b[1]));
}

#define B32(x) __float_as_uint(x)
#define PS 36   // proj X staging stride (scalar frag loads, bank-permuted)

// ---------------------------------------------------------------------------
// Prep: split + transpose W into B-fragment-tiled layout.
// ---------------------------------------------------------------------------
__global__ void wsplit_kernel(const float* __restrict__ W,
                              float* __restrict__ WTh, float* __restrict__ WTl)
{
    int idx = blockIdx.x * 256 + threadIdx.x;
    if (idx < HH * DIMV) {
        int k = idx >> 7, n = idx & 127;
        float v = W[idx];
        float h = tf32_rna(v);
        int dst = ((n >> 3) * 96 + (k >> 3)) * 64
                + ((n & 7) * 4 + (k & 3)) * 2 + ((k >> 2) & 1);
        WTh[dst] = h;
        WTl[dst] = tf32_rna(v - h);
    }
}

// ---------------------------------------------------------------------------
// Projection via 3xTF32 mma.sync. 258 blocks x 256 threads, 128 rows x 128
// cols, K=768 in 24 k32 chunks. X: reg-prefetch + tf32-split STS (PS layout,
// scalar frag loads). W: fragment-tiled cp.async double buffer -> LDS.64.
// Outputs written fragment-tiled (Q as A-frags, D as B-frags).
// smem floats: [A0 9216][A1 9216][W0 8192][W1 8192][ssb 256] = 35072
// ---------------------------------------------------------------------------
__global__ __launch_bounds__(256) void proj_kernel(
    const float* __restrict__ Qx, const float* __restrict__ Dx,
    const float* __restrict__ WTh, const float* __restrict__ WTl,
    float* __restrict__ Qh, float* __restrict__ Ql,
    float* __restrict__ Dh, float* __restrict__ Dl)
{
    extern __shared__ __align__(16) float smem[];
    float* ssb = smem + 34816;                 // [128][2]

    const int bx = blockIdx.x;
    const bool isQ = bx < 8;
    const float* X = isQ ? Qx : Dx;
    float* Yh = isQ ? Qh : Dh;
    float* Yl = isQ ? Ql : Dl;
    const size_t row0 = isQ ? (size_t)bx * 128 : (size_t)(bx - 8) * 128;

    const int tid  = threadIdx.x;
    const int warp = tid >> 5, lane = tid & 31;
    const int wm = warp >> 1, wn = warp & 1;
    const int g = lane >> 2, t = lane & 3;
    const uint32_t sbase = smem_u32(smem);

    float C[2][8][4];
#pragma unroll
    for (int mt = 0; mt < 2; mt++)
#pragma unroll
        for (int nt = 0; nt < 8; nt++)
#pragma unroll
            for (int i = 0; i < 4; i++) C[mt][nt][i] = 0.0f;

    // X prefetch registers + W cp.async prologue (chunk 0).
    float4 xr[4];
#pragma unroll
    for (int it = 0; it < 4; it++) {
        int idx = tid + 256 * it;
        int r = idx >> 3, j = idx & 7;
        xr[it] = *(const float4*)&X[(row0 + r) * HH + 4 * j];
    }
    {
        uint32_t wb = sbase + 18432 * 4;
#pragma unroll
        for (int it = 0; it < 4; it++) {
            int f = (tid + 256 * it) * 4;           // 0..4095
            int ntile = f >> 8, rest = f & 255;     // [4kt][64] contiguous
            size_t src = (size_t)(ntile * 96) * 64 + rest;
            cp16(wb + f * 4,            &WTh[src]);
            cp16(wb + (4096 + f) * 4,   &WTl[src]);
        }
    }
    CP_COMMIT();

    for (int c = 0; c < 24; c++) {
        const int buf = c & 1;
        CP_WAIT0();
        __syncthreads();

        // STS-split this chunk's X from registers (PS layout).
        {
            float* Ah = smem + buf * 9216;
            float* Al = Ah + 4608;
#pragma unroll
            for (int it = 0; it < 4; it++) {
                int idx = tid + 256 * it;
                int r = idx >> 3, j = idx & 7;
                float4 v = xr[it], h, l;
                h.x = tf32_rna(v.x); l.x = tf32_rna(v.x - h.x);
                h.y = tf32_rna(v.y); l.y = tf32_rna(v.y - h.y);
                h.z = tf32_rna(v.z); l.z = tf32_rna(v.z - h.z);
                h.w = tf32_rna(v.w); l.w = tf32_rna(v.w - h.w);
                *(float4*)&Ah[r * PS + 4 * j] = h;
                *(float4*)&Al[r * PS + 4 * j] = l;
            }
        }
        if (c < 23) {
            const int k0n = (c + 1) * 32;
#pragma unroll
            for (int it = 0; it < 4; it++) {
                int idx = tid + 256 * it;
                int r = idx >> 3, j = idx & 7;
                xr[it] = *(const float4*)&X[(row0 + r) * HH + k0n + 4 * j];
            }
            uint32_t wb = sbase + (18432 + ((c + 1) & 1) * 8192) * 4;
#pragma unroll
            for (int it = 0; it < 4; it++) {
                int f = (tid + 256 * it) * 4;
                int ntile = f >> 8, rest = f & 255;
                size_t src = ((size_t)ntile * 96 + (c + 1) * 4) * 64 + rest;
                cp16(wb + f * 4,          &WTh[src]);
                cp16(wb + (4096 + f) * 4, &WTl[src]);
            }
            CP_COMMIT();
        }
        __syncthreads();

        const float* Ash = smem + buf * 9216;
        const float* Asl = Ash + 4608;
        const float* Bsh = smem + 18432 + buf * 8192;
        const float* Bsl = Bsh + 4096;

#pragma unroll
        for (int ks = 0; ks < 4; ks++) {
            const int kk = ks * 8;
            uint32_t Ah[2][4], Al[2][4], Bh[8][2], Bl[8][2];
#pragma unroll
            for (int mt = 0; mt < 2; mt++) {
                int rb = wm * 32 + mt * 16;
                Ah[mt][0] = B32(Ash[(rb + g) * PS + kk + t]);
                Ah[mt][1] = B32(Ash[(rb + g + 8) * PS + kk + t]);
                Ah[mt][2] = B32(Ash[(rb + g) * PS + kk + t + 4]);
                Ah[mt][3] = B32(Ash[(rb + g + 8) * PS + kk + t + 4]);
                Al[mt][0] = B32(Asl[(rb + g) * PS + kk + t]);
                Al[mt][1] = B32(Asl[(rb + g + 8) * PS + kk + t]);
                Al[mt][2] = B32(Asl[(rb + g) * PS + kk + t + 4]);
                Al[mt][3] = B32(Asl[(rb + g + 8) * PS + kk + t + 4]);
            }
#pragma unroll
            for (int nt = 0; nt < 8; nt++) {
                int ntL = wn * 8 + nt;
                uint2 vh = *(const uint2*)&Bsh[(ntL * 4 + ks) * 64 + lane * 2];
                uint2 vl = *(const uint2*)&Bsl[(ntL * 4 + ks) * 64 + lane * 2];
                Bh[nt][0] = vh.x; Bh[nt][1] = vh.y;
                Bl[nt][0] = vl.x; Bl[nt][1] = vl.y;
            }
#pragma unroll
            for (int mt = 0; mt < 2; mt++)
#pragma unroll
                for (int nt = 0; nt < 8; nt++) {
                    mma_tf32(C[mt][nt], Ah[mt], Bh[nt]);   // hi*hi
                    mma_tf32(C[mt][nt], Al[mt], Bh[nt]);   // lo*hi
                    mma_tf32(C[mt][nt], Ah[mt], Bl[nt]);   // hi*lo
                }
        }
    }
    __syncthreads();

    // Row sum-of-squares (rows span wn x t x nt).
#pragma unroll
    for (int mt = 0; mt < 2; mt++) {
        float s0 = 0.0f, s1 = 0.0f;
#pragma unroll
        for (int nt = 0; nt < 8; nt++) {
            s0 += C[mt][nt][0] * C[mt][nt][0] + C[mt][nt][1] * C[mt][nt][1];
            s1 += C[mt][nt][2] * C[mt][nt][2] + C[mt][nt][3] * C[mt][nt][3];
        }
#pragma unroll
        for (int off = 1; off <= 2; off <<= 1) {
            s0 += __shfl_xor_sync(0xffffffffu, s0, off);
            s1 += __shfl_xor_sync(0xffffffffu, s1, off);
        }
        if (t == 0) {
            ssb[(wm * 32 + mt * 16 + g) * 2 + wn] = s0;
            ssb[(wm * 32 + mt * 16 + g + 8) * 2 + wn] = s1;
        }
    }
    __syncthreads();

    // Normalize + hi/lo split + FRAGMENT-TILED stores.
#pragma unroll
    for (int mt = 0; mt < 2; mt++) {
        int ra = wm * 32 + mt * 16 + g;               // local rows ra, ra+8
        float ia = 1.0f / fmaxf(sqrtf(ssb[ra * 2] + ssb[ra * 2 + 1]), 1e-12f);
        float ib = 1.0f / fmaxf(sqrtf(ssb[(ra + 8) * 2] + ssb[(ra + 8) * 2 + 1]), 1e-12f);
        size_t gr = row0 + ra;                        // (gr>>3)&1 == 0
#pragma unroll
        for (int nt = 0; nt < 8; nt++) {
            int c0 = wn * 64 + nt * 8 + 2 * t;
            float v0 = C[mt][nt][0] * ia, v1 = C[mt][nt][1] * ia;
            float v2 = C[mt][nt][2] * ib, v3 = C[mt][nt][3] * ib;
            float h0 = tf32_rna(v0), h1 = tf32_rna(v1);
            float h2 = tf32_rna(v2), h3 = tf32_rna(v3);
            float l0 = tf32_rna(v0 - h0), l1 = tf32_rna(v1 - h1);
            float l2 = tf32_rna(v2 - h2), l3 = tf32_rna(v3 - h3);
            if (isQ) {
                // A-frag: v0,v2 and v1,v3 land adjacent -> STG.64 pairs.
                size_t tb = (((gr >> 4) * 16) + (c0 >> 3)) * 128
                          + ((gr & 7) * 4 + (c0 & 3)) * 4 + ((c0 >> 2) & 1) * 2;
                *(float2*)&Yh[tb]     = make_float2(h0, h2);
                *(float2*)&Yh[tb + 4] = make_float2(h1, h3);
                *(float2*)&Yl[tb]     = make_float2(l0, l2);
                *(float2*)&Yl[tb + 4] = make_float2(l1, l3);
            } else {
                // B-frag: rows ra and ra+8 fall in consecutive ntiles.
                size_t tb0 = ((gr >> 3) * 16 + (c0 >> 3)) * 64
                           + ((gr & 7) * 4 + (c0 & 3)) * 2 + ((c0 >> 2) & 1);
                size_t tb1 = tb0 + 1024;
                Yh[tb0] = h0; Yh[tb0 + 2] = h1; Yh[tb1] = h2; Yh[tb1 + 2] = h3;
                Yl[tb0] = l0; Yl[tb0 + 2] = l1; Yl[tb1] = l2; Yl[tb1 + 2] = l3;
            }
        }
    }
}

// ---------------------------------------------------------------------------
// Fused scoring via 3xTF32 mma.sync, fragment-tiled operands (LDS.128/.64),
// k16 double-buffered cp.async, gumbel staged to a dedicated smem region.
// Block = (4q, 1d): M=128, N=160, K=128 in eight k16 chunks. 1600 x 256.
// Warps (2 wm x 4 wn): warp tile 64m x 40n -> mt 0..3, nt 0..4.
// smem floats: [buf0 9216][buf1 9216][gum 20480][dmask 160][qmask 128]
//              [zbuf 512][sbuf 512] = 40224 (157 KB)
// ---------------------------------------------------------------------------
__global__ __launch_bounds__(256) void score_kernel(
    const float* __restrict__ gumbel,
    const float* __restrict__ q_mask,
    const float* __restrict__ d_mask,
    float* __restrict__ out)
{
    extern __shared__ __align__(16) float smem[];
    float* gum_s   = smem + 18432;          // [128][160]
    float* dmask_s = smem + 38912;          // [160]
    float* qmask_s = smem + 39072;          // [128]
    float* zbuf    = smem + 39200;          // [128][4]
    float* sbuf    = smem + 39712;          // [128][4]

    const int bx = blockIdx.x;
    const int d  = bx % ND_;
    const int qg = bx / ND_;                // 0..7
    const int tid  = threadIdx.x;
    const int warp = tid >> 5, lane = tid & 31;
    const int wm = warp >> 2, wn = warp & 3;
    const int g = lane >> 2, t = lane & 3;
    const uint32_t sbase = smem_u32(smem);

    if (tid < NN)  dmask_s[tid] = d_mask[(size_t)d * NN + tid];
    if (tid < 128) qmask_s[tid] = q_mask[(size_t)qg * 128 + tid];

    float C[4][5][4];
#pragma unroll
    for (int mt = 0; mt < 4; mt++)
#pragma unroll
        for (int nt = 0; nt < 5; nt++)
#pragma unroll
            for (int i = 0; i < 4; i++) C[mt][nt][i] = 0.0f;

    // Unified chunk staging: 2304 cp16 (A-hi 512 | A-lo 512 | B-hi 640 | B-lo 640)
    auto stage_chunk = [&](int c, uint32_t bb) {
#pragma unroll
        for (int i = 0; i < 9; i++) {
            int idx = tid + 256 * i;
            if (idx < 512) {
                int f = idx * 4;
                cp16(bb + f * 4, &g_Qh[((size_t)(qg * 8 + (f >> 8)) * 16 + c * 2) * 128 + (f & 255)]);
            } else if (idx < 1024) {
                int f = (idx - 512) * 4;
                cp16(bb + (2048 + f) * 4, &g_Ql[((size_t)(qg * 8 + (f >> 8)) * 16 + c * 2) * 128 + (f & 255)]);
            } else if (idx < 1664) {
                int f = (idx - 1024) * 4;
                cp16(bb + (4096 + f) * 4, &g_Dh[((size_t)(d * 20 + (f >> 7)) * 16 + c * 2) * 64 + (f & 127)]);
            } else {
                int f = (idx - 1664) * 4;
                cp16(bb + (6656 + f) * 4, &g_Dl[((size_t)(d * 20 + (f >> 7)) * 16 + c * 2) * 64 + (f & 127)]);
            }
        }
    };

    stage_chunk(0, sbase);
    CP_COMMIT();

    for (int c = 0; c < 8; c++) {
        const int buf = c & 1;
        CP_WAIT0();
        __syncthreads();

        if (c < 7) {
            stage_chunk(c + 1, sbase + ((c + 1) & 1) * 9216 * 4);
            if (c == 5) {
                // gumbel: 5120 cp16, 20/thread, into dedicated region.
#pragma unroll
                for (int it = 0; it < 20; it++) {
                    int idx = tid + 256 * it;
                    int r = idx / 40, j = idx - r * 40;
                    int q = qg * 4 + (r >> 5), m = r & 31;
                    cp16(sbase + (18432 + r * 160 + 4 * j) * 4,
                         gumbel + (((size_t)q * ND_ + d) * MM + m) * NN + 4 * j);
                }
            }
            CP_COMMIT();
        }

        const float* st = smem + buf * 9216;
#pragma unroll
        for (int ks = 0; ks < 2; ks++) {
            uint32_t Ah[4][4], Al[4][4], Bh[5][2], Bl[5][2];
#pragma unroll
            for (int mt = 0; mt < 4; mt++) {
                int mo = ((wm * 4 + mt) * 2 + ks) * 128 + lane * 4;
                uint4 vh = *(const uint4*)&st[mo];
                uint4 vl = *(const uint4*)&st[2048 + mo];
                Ah[mt][0] = vh.x; Ah[mt][1] = vh.y; Ah[mt][2] = vh.z; Ah[mt][3] = vh.w;
                Al[mt][0] = vl.x; Al[mt][1] = vl.y; Al[mt][2] = vl.z; Al[mt][3] = vl.w;
            }
#pragma unroll
            for (int nt = 0; nt < 5; nt++) {
                int no = ((wn * 5 + nt) * 2 + ks) * 64 + lane * 2;
                uint2 vh = *(const uint2*)&st[4096 + no];
                uint2 vl = *(const uint2*)&st[6656 + no];
                Bh[nt][0] = vh.x; Bh[nt][1] = vh.y;
                Bl[nt][0] = vl.x; Bl[nt][1] = vl.y;
            }
#pragma unroll
            for (int mt = 0; mt < 4; mt++)
#pragma unroll
                for (int nt = 0; nt < 5; nt++) {
                    mma_tf32(C[mt][nt], Ah[mt], Bh[nt]);   // hi*hi
                    mma_tf32(C[mt][nt], Al[mt], Bh[nt]);   // lo*hi
                    mma_tf32(C[mt][nt], Ah[mt], Bl[nt]);   // hi*lo
                }
        }
    }

    // Epilogue: per m-row masked gumbel-argmax over this warp's 40 n.
#pragma unroll
    for (int mt = 0; mt < 4; mt++) {
#pragma unroll
        for (int h = 0; h < 2; h++) {
            const int r = wm * 64 + mt * 16 + g + h * 8;   // local row 0..127
            const float* grow = gum_s + r * 160;
            float bz = -3.0e38f, bs = 0.0f;
#pragma unroll
            for (int nt = 0; nt < 5; nt++) {
                const int n = wn * 40 + nt * 8 + 2 * t;
                float2 dm = *(const float2*)&dmask_s[n];
                float2 gv = *(const float2*)&grow[n];
                float c0 = C[mt][nt][2 * h], c1 = C[mt][nt][2 * h + 1];
                float s0 = c0 * dm.x + (1.0f - dm.x) * NEGV;  // exact select
                float s1 = c1 * dm.y + (1.0f - dm.y) * NEGV;
                float z0 = s0 * 10.0f + gv.x;                 // TEMP=0.1
                float z1 = s1 * 10.0f + gv.y;
                if (z0 > bz) { bz = z0; bs = s0; }
                if (z1 > bz) { bz = z1; bs = s1; }
            }
#pragma unroll
            for (int off = 1; off <= 2; off <<= 1) {          // reduce over t
                float zo = __shfl_xor_sync(0xffffffffu, bz, off);
                float so = __shfl_xor_sync(0xffffffffu, bs, off);
                if (zo > bz) { bz = zo; bs = so; }
            }
            if (t == 0) { zbuf[r * 4 + wn] = bz; sbuf[r * 4 + wn] = bs; }
        }
    }
    __syncthreads();

    if (tid < 128) {
        const int r = tid;
        float bz = zbuf[4 * r], bs = sbuf[4 * r];
#pragma unroll
        for (int w = 1; w < 4; w++) {
            float z = zbuf[4 * r + w];
            if (z > bz) { bz = z; bs = sbuf[4 * r + w]; }
        }
        float p = qmask_s[r] * bs;
#pragma unroll
        for (int off = 16; off >= 1; off >>= 1)
            p += __shfl_xor_sync(0xffffffffu, p, off);        // sum over m
        if ((r & 31) == 0)
            out[(size_t)(qg * 4 + (r >> 5)) * ND_ + d] = p;
    }
}

// ---------------------------------------------------------------------------
extern "C" void kernel_launch(void* const* d_in, const int* in_sizes, int n_in,
                              void* d_out, int out_size)
{
    const float* Q      = (const float*)d_in[0];  // (32,32,768)
    const float* D      = (const float*)d_in[1];  // (200,160,768)
    const float* q_mask = (const float*)d_in[2];  // (32,32)
    const float* d_mask = (const float*)d_in[3];  // (200,160)
    const float* gumbel = (const float*)d_in[4];  // (32,200,32,160)
    const float* W      = (const float*)d_in[5];  // (768,128)
    float* out = (float*)d_out;                   // (32,200)

    float *Qh, *Ql, *Dh, *Dl, *WTh, *WTl;
    cudaGetSymbolAddress((void**)&Qh,  g_Qh);
    cudaGetSymbolAddress((void**)&Ql,  g_Ql);
    cudaGetSymbolAddress((void**)&Dh,  g_Dh);
    cudaGetSymbolAddress((void**)&Dl,  g_Dl);
    cudaGetSymbolAddress((void**)&WTh, g_WTh);
    cudaGetSymbolAddress((void**)&WTl, g_WTl);

    // 1) Split + transpose W into B-fragment tiles.
    wsplit_kernel<<<(HH * DIMV + 255) / 256, 256>>>(W, WTh, WTl);

    // 2) Projection (8 Q-blocks + 250 D-blocks of 128 rows).
    const int proj_smem = 35072 * sizeof(float);
    cudaFuncSetAttribute(proj_kernel,
                         cudaFuncAttributeMaxDynamicSharedMemorySize, proj_smem);
    proj_kernel<<<258, 256, proj_smem>>>(Q, D, WTh, WTl, Qh, Ql, Dh, Dl);

    // 3) Fused sim + gumbel-argmax + score.
    const int score_smem = 40224 * sizeof(float);
    cudaFuncSetAttribute(score_kernel,
                         cudaFuncAttributeMaxDynamicSharedMemorySize, score_smem);
    score_kernel<<<(NQ / 4) * ND_, 256, score_smem>>>(gumbel, q_mask, d_mask, out);
}